// round 4
// baseline (speedup 1.0000x reference)
#include <cuda_runtime.h>
#include <cuda_bf16.h>

// MaxPool2d k=2 s=2 on fp32 NCHW (32, 96, 224, 224) -> (32, 96, 112, 112).
// Pure streaming, DRAM-bound (R2: 89.4% DRAM, 7081 GB/s).
// This round: fuse the per-row float4 pair into a single 256-bit load
// (ld.global.nc.v8.f32, sm_100+) so each warp-level load is a fully
// contiguous 1024 B sweep instead of two half-sector-strided LDG.128s.
//
//   NC = 32*96 = 3072, H = W = 224, OH = OW = 112
//   one thread = one output float4 (4 output pixels)
//   per thread: 2x v8 load (32 B each, rows 2*oy and 2*oy+1), 1x float4 store

#define NC_    3072
#define W_     224
#define OH_    112
#define OW4_   28            // float4s per output row
#define ROWF4_ (W_ / 4)      // 56 float4s per input row
#define TOTAL_ (NC_ * OH_ * OW4_)

__global__ __launch_bounds__(256)
void maxpool2x2_kernel(const float* __restrict__ x, float4* __restrict__ out) {
    unsigned int idx = blockIdx.x * 256u + threadIdx.x;   // == output float4 index
    if (idx >= TOTAL_) return;

    unsigned int ox4 = idx % OW4_;           // which float4 within output row
    unsigned int t   = idx / OW4_;
    unsigned int oy  = t % OH_;
    unsigned int nc  = t / OH_;

    // Input byte base: plane nc, row 2*oy, float col 8*ox4. 32-byte aligned.
    const float* p0 = x + (size_t)nc * (W_ * W_) + (size_t)(2u * oy) * W_ + 8u * ox4;
    const float* p1 = p0 + W_;

    float a0, a1, a2, a3, a4, a5, a6, a7;   // row 2*oy,   8 consecutive floats
    float b0, b1, b2, b3, b4, b5, b6, b7;   // row 2*oy+1, 8 consecutive floats

    asm volatile("ld.global.nc.v8.f32 {%0,%1,%2,%3,%4,%5,%6,%7}, [%8];"
        : "=f"(a0), "=f"(a1), "=f"(a2), "=f"(a3),
          "=f"(a4), "=f"(a5), "=f"(a6), "=f"(a7)
        : "l"(p0));
    asm volatile("ld.global.nc.v8.f32 {%0,%1,%2,%3,%4,%5,%6,%7}, [%8];"
        : "=f"(b0), "=f"(b1), "=f"(b2), "=f"(b3),
          "=f"(b4), "=f"(b5), "=f"(b6), "=f"(b7)
        : "l"(p1));

    float4 r;
    r.x = fmaxf(fmaxf(a0, a1), fmaxf(b0, b1));
    r.y = fmaxf(fmaxf(a2, a3), fmaxf(b2, b3));
    r.z = fmaxf(fmaxf(a4, a5), fmaxf(b4, b5));
    r.w = fmaxf(fmaxf(a6, a7), fmaxf(b6, b7));

    out[idx] = r;
}

extern "C" void kernel_launch(void* const* d_in, const int* in_sizes, int n_in,
                              void* d_out, int out_size) {
    const float* x = (const float*)d_in[0];
    float4* out = (float4*)d_out;
    const int threads = 256;
    const int blocks = (TOTAL_ + threads - 1) / threads;   // 37632
    maxpool2x2_kernel<<<blocks, threads>>>(x, out);
}